// round 9
// baseline (speedup 1.0000x reference)
#include <cuda_runtime.h>
#include <cuda_fp16.h>
#include <cstdint>

#define N_NODES 50000
#define NNZ_C   800000
#define N_ADJ   6
#define K_DIM   256
#define H_DIM   128
#define LN_EPS  1e-5f

// ---------------------------------------------------------------------------
// Device-global scratch
//   g_half[0..2] : fp16 gather sources for s0, s1, s2
//   g_acc [0..2] : fp32 results s1, s2, s3 (plain stores, no atomics)
//   CSR: g_wcur (counts->cursors), g_rowptr, g_edges packed (col, val)
// ---------------------------------------------------------------------------
__device__ __half g_half[3][(size_t)N_NODES * H_DIM];
__device__ float  g_acc[3][(size_t)N_NODES * H_DIM];
__device__ int    g_wcur[N_ADJ][N_NODES];
__device__ int    g_rowptr[N_ADJ][N_NODES + 1];
__device__ int2   g_edges[N_ADJ][NNZ_C];

// ---------------------------------------------------------------------------
// CSR build: zero counters -> histogram -> scan -> scatter(pack col+val)
// ---------------------------------------------------------------------------
__global__ void zero_cnt_kernel() {
    const int i = blockIdx.x * blockDim.x + threadIdx.x;
    if (i < N_ADJ * N_NODES) (&g_wcur[0][0])[i] = 0;
}

// grid: (NNZ_C/256, N_ADJ)
__global__ __launch_bounds__(256) void hist_kernel(const int* __restrict__ rows_base) {
    const int e = blockIdx.x * blockDim.x + threadIdx.x;
    const int* rows = rows_base + (size_t)blockIdx.y * NNZ_C;
    if (e < NNZ_C) {
        const int row = __ldg(rows + e);
        atomicAdd(&g_wcur[blockIdx.y][row], 1);
    }
}

// One block per adjacency: 256 threads, contiguous row chunks + block scan.
__global__ __launch_bounds__(256) void scan_kernel() {
    const int a = blockIdx.x;
    const int t = threadIdx.x;
    const int CHUNK = (N_NODES + 255) / 256;
    const int start = t * CHUNK;
    const int end = min(start + CHUNK, N_NODES);

    int sum = 0;
    for (int r = start; r < end; r++) sum += g_wcur[a][r];

    __shared__ int sh[256];
    sh[t] = sum;
    __syncthreads();
    for (int off = 1; off < 256; off <<= 1) {
        int v = (t >= off) ? sh[t - off] : 0;
        __syncthreads();
        sh[t] += v;
        __syncthreads();
    }
    int run = sh[t] - sum;
    for (int r = start; r < end; r++) {
        const int c = g_wcur[a][r];
        g_rowptr[a][r] = run;
        g_wcur[a][r] = run;          // becomes scatter cursor
        run += c;
    }
    if (t == 255) g_rowptr[a][N_NODES] = run;
}

// grid: (NNZ_C/256, N_ADJ)
__global__ __launch_bounds__(256) void scatter_kernel(const int*   __restrict__ rows_base,
                                                      const int*   __restrict__ cols_base,
                                                      const float* __restrict__ vals_base) {
    const int a = blockIdx.y;
    const int e = blockIdx.x * blockDim.x + threadIdx.x;
    const size_t base = (size_t)a * NNZ_C;
    if (e < NNZ_C) {
        const int   row = __ldg(rows_base + base + e);
        const int   col = __ldg(cols_base + base + e);
        const float v   = __ldg(vals_base + base + e);
        const int pos = atomicAdd(&g_wcur[a][row], 1);
        g_edges[a][pos] = make_int2(col, __float_as_int(v));
    }
}

// ---------------------------------------------------------------------------
// GEMM: g_half[0] = fp16(X[50000,256] @ W[256,128] + b)
// ---------------------------------------------------------------------------
__global__ __launch_bounds__(256) void gemm_kernel(const float* __restrict__ X,
                                                   const float* __restrict__ W,
                                                   const float* __restrict__ bias) {
    __shared__ float As[8][128];
    __shared__ float Bs[8][128];

    const int tid = threadIdx.x;
    const int tx = tid & 15;
    const int ty = tid >> 4;
    const int row0 = blockIdx.x * 128;

    const int arow = tid >> 1;
    const int ak   = (tid & 1) * 4;
    const int grow = min(row0 + arow, N_NODES - 1);
    const int brow = tid >> 5;
    const int bcol = (tid & 31) * 4;

    float acc[8][8];
#pragma unroll
    for (int i = 0; i < 8; i++)
#pragma unroll
        for (int j = 0; j < 8; j++) acc[i][j] = 0.f;

    for (int k0 = 0; k0 < K_DIM; k0 += 8) {
        const float4 av = *reinterpret_cast<const float4*>(
            X + (size_t)grow * K_DIM + k0 + ak);
        const float4 bv = *reinterpret_cast<const float4*>(
            W + (size_t)(k0 + brow) * H_DIM + bcol);
        __syncthreads();
        As[ak + 0][arow] = av.x;
        As[ak + 1][arow] = av.y;
        As[ak + 2][arow] = av.z;
        As[ak + 3][arow] = av.w;
        *reinterpret_cast<float4*>(&Bs[brow][bcol]) = bv;
        __syncthreads();

#pragma unroll
        for (int kk = 0; kk < 8; kk++) {
            float a[8], b[8];
            const float4 a0 = *reinterpret_cast<const float4*>(&As[kk][ty * 8]);
            const float4 a1 = *reinterpret_cast<const float4*>(&As[kk][ty * 8 + 4]);
            const float4 b0 = *reinterpret_cast<const float4*>(&Bs[kk][tx * 8]);
            const float4 b1 = *reinterpret_cast<const float4*>(&Bs[kk][tx * 8 + 4]);
            a[0]=a0.x; a[1]=a0.y; a[2]=a0.z; a[3]=a0.w;
            a[4]=a1.x; a[5]=a1.y; a[6]=a1.z; a[7]=a1.w;
            b[0]=b0.x; b[1]=b0.y; b[2]=b0.z; b[3]=b0.w;
            b[4]=b1.x; b[5]=b1.y; b[6]=b1.z; b[7]=b1.w;
#pragma unroll
            for (int i = 0; i < 8; i++)
#pragma unroll
                for (int j = 0; j < 8; j++) acc[i][j] += a[i] * b[j];
        }
    }

    const int colb = tx * 8;
    const float4 bia0 = *reinterpret_cast<const float4*>(bias + colb);
    const float4 bia1 = *reinterpret_cast<const float4*>(bias + colb + 4);
#pragma unroll
    for (int i = 0; i < 8; i++) {
        const int row = row0 + ty * 8 + i;
        if (row < N_NODES) {
            __half2 p0 = __floats2half2_rn(acc[i][0] + bia0.x, acc[i][1] + bia0.y);
            __half2 p1 = __floats2half2_rn(acc[i][2] + bia0.z, acc[i][3] + bia0.w);
            __half2 p2 = __floats2half2_rn(acc[i][4] + bia1.x, acc[i][5] + bia1.y);
            __half2 p3 = __floats2half2_rn(acc[i][6] + bia1.z, acc[i][7] + bia1.w);
            uint4 pk;
            pk.x = *reinterpret_cast<const unsigned int*>(&p0);
            pk.y = *reinterpret_cast<const unsigned int*>(&p1);
            pk.z = *reinterpret_cast<const unsigned int*>(&p2);
            pk.w = *reinterpret_cast<const unsigned int*>(&p3);
            *reinterpret_cast<uint4*>(&g_half[0][(size_t)row * H_DIM + colb]) = pk;
        }
    }
}

// ---------------------------------------------------------------------------
// CSR SpMM step: one warp per destination row, HALF-WARP per edge.
// 16 lanes cover the 256B fp16 source row (uint4 each), so one warp-wide
// LDG.128 gathers TWO edges at once. No atomics, no stores in the loop ->
// compiler can pipeline gathers deeply. 8 fp32 accumulators per thread,
// half-warps combined via shfl, single 512B row store.
// accum=0: dst = sum; accum=1: dst += sum.
// ---------------------------------------------------------------------------
__global__ __launch_bounds__(256) void csr_step_kernel(const int* __restrict__ idxp,
                                                       int src_id, int dst_id,
                                                       int accum) {
    const int lane = threadIdx.x & 31;
    const int half = lane >> 4;          // 0 or 1: which edge stream
    const int hl   = lane & 15;          // position within half-warp
    const int row  = (blockIdx.x * blockDim.x + threadIdx.x) >> 5;
    if (row >= N_NODES) return;

    const int a = __ldg(idxp);
    const __half* __restrict__ src = g_half[src_id];
    float*        __restrict__ dst = g_acc[dst_id];
    const int2*   __restrict__ el  = g_edges[a];

    const int beg = __ldg(&g_rowptr[a][row]);
    const int end = __ldg(&g_rowptr[a][row + 1]);

    float acc[8];
#pragma unroll
    for (int k = 0; k < 8; k++) acc[k] = 0.f;

    // Each half-warp walks every other edge; the warp-wide LDG covers 2 edges.
#pragma unroll 2
    for (int e = beg + half; e < end; e += 2) {
        const int2 cv = __ldg(el + e);        // broadcast within half-warp
        const float val = __int_as_float(cv.y);
        const uint4 hv = __ldg(reinterpret_cast<const uint4*>(
                                   src + (size_t)cv.x * H_DIM) + hl);
        const float2 f0 = __half22float2(*reinterpret_cast<const __half2*>(&hv.x));
        const float2 f1 = __half22float2(*reinterpret_cast<const __half2*>(&hv.y));
        const float2 f2 = __half22float2(*reinterpret_cast<const __half2*>(&hv.z));
        const float2 f3 = __half22float2(*reinterpret_cast<const __half2*>(&hv.w));
        acc[0] += val * f0.x; acc[1] += val * f0.y;
        acc[2] += val * f1.x; acc[3] += val * f1.y;
        acc[4] += val * f2.x; acc[5] += val * f2.y;
        acc[6] += val * f3.x; acc[7] += val * f3.y;
    }

    // Combine the two half-warps (lane i += lane i+16)
#pragma unroll
    for (int k = 0; k < 8; k++)
        acc[k] += __shfl_down_sync(0xFFFFFFFFu, acc[k], 16);

    if (half == 0) {
        float* dp = dst + (size_t)row * H_DIM + hl * 8;
        if (accum) {
            const float4 d0 = *reinterpret_cast<const float4*>(dp);
            const float4 d1 = *reinterpret_cast<const float4*>(dp + 4);
            acc[0] += d0.x; acc[1] += d0.y; acc[2] += d0.z; acc[3] += d0.w;
            acc[4] += d1.x; acc[5] += d1.y; acc[6] += d1.z; acc[7] += d1.w;
        }
        float4 o0, o1;
        o0.x = acc[0]; o0.y = acc[1]; o0.z = acc[2]; o0.w = acc[3];
        o1.x = acc[4]; o1.y = acc[5]; o1.z = acc[6]; o1.w = acc[7];
        *reinterpret_cast<float4*>(dp)     = o0;
        *reinterpret_cast<float4*>(dp + 4) = o1;
    }
}

// ---------------------------------------------------------------------------
// Convert fp32 result sid (s1 or s2) into fp16 mirror sid+1
// ---------------------------------------------------------------------------
__global__ __launch_bounds__(256) void tohalf_kernel(int sid) {
    const size_t i = (size_t)blockIdx.x * blockDim.x + threadIdx.x;
    const size_t n4 = (size_t)N_NODES * H_DIM / 4;
    if (i >= n4) return;
    const float4 v = reinterpret_cast<const float4*>(&g_acc[sid][0])[i];
    __half2 h0 = __floats2half2_rn(v.x, v.y);
    __half2 h1 = __floats2half2_rn(v.z, v.w);
    uint2 pk;
    pk.x = *reinterpret_cast<const unsigned int*>(&h0);
    pk.y = *reinterpret_cast<const unsigned int*>(&h1);
    reinterpret_cast<uint2*>(&g_half[sid + 1][0])[i] = pk;
}

// ---------------------------------------------------------------------------
// LayerNorm + exact-erf GELU, one warp per row (reads fp32 s3)
// ---------------------------------------------------------------------------
__global__ __launch_bounds__(256) void ln_gelu_kernel(const float* __restrict__ gamma,
                                                      const float* __restrict__ beta,
                                                      float* __restrict__ out) {
    const int warp = (blockIdx.x * blockDim.x + threadIdx.x) >> 5;
    const int lane = threadIdx.x & 31;
    if (warp >= N_NODES) return;

    const float* yrow = g_acc[2] + (size_t)warp * H_DIM;
    const float4 v = *reinterpret_cast<const float4*>(yrow + lane * 4);

    float s  = v.x + v.y + v.z + v.w;
    float sq = v.x * v.x + v.y * v.y + v.z * v.z + v.w * v.w;
#pragma unroll
    for (int o = 16; o; o >>= 1) {
        s  += __shfl_xor_sync(0xFFFFFFFFu, s,  o);
        sq += __shfl_xor_sync(0xFFFFFFFFu, sq, o);
    }
    const float mean = s * (1.f / H_DIM);
    const float var  = sq * (1.f / H_DIM) - mean * mean;
    const float rstd = rsqrtf(var + LN_EPS);

    const float4 g = *reinterpret_cast<const float4*>(gamma + lane * 4);
    const float4 b = *reinterpret_cast<const float4*>(beta  + lane * 4);

    auto gelu = [](float t) {
        return 0.5f * t * (1.f + erff(t * 0.7071067811865476f));
    };
    float4 r;
    r.x = gelu((v.x - mean) * rstd * g.x + b.x);
    r.y = gelu((v.y - mean) * rstd * g.y + b.y);
    r.z = gelu((v.z - mean) * rstd * g.z + b.z);
    r.w = gelu((v.w - mean) * rstd * g.w + b.w);

    *reinterpret_cast<float4*>(out + (size_t)warp * H_DIM + lane * 4) = r;
}

// ---------------------------------------------------------------------------
// kernel_launch
// inputs: x, adj_rows, adj_cols, adj_vals, idxes_seq, idxes_res,
//         W, b, gamma, beta
// ---------------------------------------------------------------------------
extern "C" void kernel_launch(void* const* d_in, const int* in_sizes, int n_in,
                              void* d_out, int out_size) {
    const float* x        = (const float*)d_in[0];
    const int*   adj_rows = (const int*)  d_in[1];
    const int*   adj_cols = (const int*)  d_in[2];
    const float* adj_vals = (const float*)d_in[3];
    const int*   idx_seq  = (const int*)  d_in[4];
    const int*   idx_res  = (const int*)  d_in[5];
    const float* W        = (const float*)d_in[6];
    const float* b        = (const float*)d_in[7];
    const float* gamma    = (const float*)d_in[8];
    const float* beta     = (const float*)d_in[9];
    float*       out      = (float*)d_out;

    // ---- CSR build (also packs (col,val); kills zip + zero kernels) ----
    dim3 egrid((NNZ_C + 255) / 256, N_ADJ);
    zero_cnt_kernel<<<(N_ADJ * N_NODES + 255) / 256, 256>>>();
    hist_kernel<<<egrid, 256>>>(adj_rows);
    scan_kernel<<<N_ADJ, 256>>>();
    scatter_kernel<<<egrid, 256>>>(adj_rows, adj_cols, adj_vals);

    // ---- affine -> fp16 s0 ----
    gemm_kernel<<<(N_NODES + 127) / 128, 256>>>(x, W, b);

    // ---- propagation: CSR steps (no atomics) ----
    const int RGRID = (N_NODES * 32 + 255) / 256;    // one warp per row
    const int CVT_GRID = (N_NODES * H_DIM / 4 + 255) / 256;

    // s1 (acc0) = A[seq0] @ h0
    csr_step_kernel<<<RGRID, 256>>>(idx_seq + 0, 0, 0, 0);
    tohalf_kernel<<<CVT_GRID, 256>>>(0);             // h1 = fp16(s1)
    // s2 (acc1) = A[seq1] @ h1 + A[res0] @ h0
    csr_step_kernel<<<RGRID, 256>>>(idx_seq + 1, 1, 1, 0);
    csr_step_kernel<<<RGRID, 256>>>(idx_res + 0, 0, 1, 1);
    tohalf_kernel<<<CVT_GRID, 256>>>(1);             // h2 = fp16(s2)
    // s3 (acc2) = A[seq2] @ h2 + A[res1] @ h0 + A[res2] @ h1
    csr_step_kernel<<<RGRID, 256>>>(idx_seq + 2, 2, 2, 0);
    csr_step_kernel<<<RGRID, 256>>>(idx_res + 1, 0, 2, 1);
    csr_step_kernel<<<RGRID, 256>>>(idx_res + 2, 1, 2, 1);

    ln_gelu_kernel<<<(N_NODES * 32 + 255) / 256, 256>>>(gamma, beta, out);
}

// round 12
// speedup vs baseline: 1.1938x; 1.1938x over previous
#include <cuda_runtime.h>
#include <cuda_fp16.h>
#include <mma.h>
#include <cstdint>

using namespace nvcuda;

#define N_NODES 50000
#define NNZ_C   800000
#define N_ADJ   6
#define K_DIM   256
#define H_DIM   128
#define LN_EPS  1e-5f

// ---------------------------------------------------------------------------
// Device-global scratch
//   g_half[0..2] : fp16 gather sources for s0, s1, s2
//   g_acc [0..2] : fp32 RED accumulators for s1, s2, s3
// ---------------------------------------------------------------------------
__device__ __half g_half[3][(size_t)N_NODES * H_DIM];
__device__ float  g_acc[3][(size_t)N_NODES * H_DIM];
__device__ int2   g_ecv[N_ADJ][NNZ_C];                 // zipped (col, val bits)

// ---------------------------------------------------------------------------
// Zero the fp32 accumulators each call
// ---------------------------------------------------------------------------
__global__ void zero_kernel() {
    const size_t n4 = (size_t)3 * N_NODES * H_DIM / 4;
    float4* p = reinterpret_cast<float4*>(&g_acc[0][0]);
    const float4 z = make_float4(0.f, 0.f, 0.f, 0.f);
    for (size_t i = (size_t)blockIdx.x * blockDim.x + threadIdx.x; i < n4;
         i += (size_t)gridDim.x * blockDim.x)
        p[i] = z;
}

// ---------------------------------------------------------------------------
// Zip cols+vals into int2 (streaming)
// ---------------------------------------------------------------------------
__global__ __launch_bounds__(256) void zip_kernel(const int*   __restrict__ cols_base,
                                                  const float* __restrict__ vals_base) {
    const size_t i = (size_t)blockIdx.x * blockDim.x + threadIdx.x;
    if (i < (size_t)N_ADJ * NNZ_C)
        (&g_ecv[0][0])[i] = make_int2(__ldg(cols_base + i),
                                      __float_as_int(__ldg(vals_base + i)));
}

// ---------------------------------------------------------------------------
// Tensor-core GEMM via nvcuda::wmma (no inline PTX):
//   g_half[0] = fp16(X[50000,256] @ W[256,128] + b)
// BM=128, BN=128(=H_DIM), BK=64; 256 threads = 8 warps (4 x 2).
// Warp tile 32x64 = 2x4 wmma 16x16x16 fragments, fp32 accumulate.
// Smem pitch GP=80 halves (160B rows): 32B-aligned fragment pointers,
// ldm multiple of 8.
// ---------------------------------------------------------------------------
#define GP 80   // smem pitch in halves

__global__ __launch_bounds__(256) void gemm_kernel(const float* __restrict__ X,
                                                   const float* __restrict__ W,
                                                   const float* __restrict__ bias) {
    __shared__ __half A_sm[128 * GP];   // [m][k], row-major
    __shared__ __half B_sm[128 * GP];   // [n][k] == col-major B (k x n)

    const int tid  = threadIdx.x;
    const int lane = tid & 31;
    const int wid  = tid >> 5;
    const int warp_m = wid >> 1;         // 0..3 -> row offset *32
    const int warp_n = wid & 1;          // 0..1 -> col offset *64
    const int row0 = blockIdx.x * 128;

    wmma::fragment<wmma::accumulator, 16, 16, 16, float> acc[2][4];
#pragma unroll
    for (int mt = 0; mt < 2; mt++)
#pragma unroll
        for (int nt = 0; nt < 4; nt++)
            wmma::fill_fragment(acc[mt][nt], 0.f);

    for (int k0 = 0; k0 < K_DIM; k0 += 64) {
        // ---- load A tile: X[row0..row0+127][k0..k0+63] fp32 -> fp16 smem ----
#pragma unroll
        for (int i = 0; i < 8; i++) {
            const int idx = tid + i * 256;       // 0..2047 float4s
            const int r  = idx >> 4;             // 16 float4 per row
            const int c4 = idx & 15;
            const int grow = min(row0 + r, N_NODES - 1);
            const float4 v = __ldg(reinterpret_cast<const float4*>(
                X + (size_t)grow * K_DIM + k0 + c4 * 4));
            __half2 h0 = __floats2half2_rn(v.x, v.y);
            __half2 h1 = __floats2half2_rn(v.z, v.w);
            uint2 pk;
            pk.x = *reinterpret_cast<const unsigned int*>(&h0);
            pk.y = *reinterpret_cast<const unsigned int*>(&h1);
            *reinterpret_cast<uint2*>(&A_sm[r * GP + c4 * 4]) = pk;
        }
        // ---- load B tile: W[k0..k0+63][0..127] -> B_sm[n][k] ----
#pragma unroll
        for (int i = 0; i < 8; i++) {
            const int idx = tid + i * 256;       // 0..2047 float4s
            const int k  = idx >> 5;             // 32 float4 per k-row
            const int n4 = idx & 31;
            const float4 v = __ldg(reinterpret_cast<const float4*>(
                W + (size_t)(k0 + k) * H_DIM + n4 * 4));
            B_sm[(n4 * 4 + 0) * GP + k] = __float2half_rn(v.x);
            B_sm[(n4 * 4 + 1) * GP + k] = __float2half_rn(v.y);
            B_sm[(n4 * 4 + 2) * GP + k] = __float2half_rn(v.z);
            B_sm[(n4 * 4 + 3) * GP + k] = __float2half_rn(v.w);
        }
        __syncthreads();

        // ---- 4 k-steps of 16 ----
#pragma unroll
        for (int ks = 0; ks < 4; ks++) {
            const int kk = ks * 16;
            wmma::fragment<wmma::matrix_a, 16, 16, 16, __half, wmma::row_major> af[2];
#pragma unroll
            for (int mt = 0; mt < 2; mt++)
                wmma::load_matrix_sync(
                    af[mt], &A_sm[(warp_m * 32 + mt * 16) * GP + kk], GP);
#pragma unroll
            for (int nt = 0; nt < 4; nt++) {
                wmma::fragment<wmma::matrix_b, 16, 16, 16, __half, wmma::col_major> bf;
                wmma::load_matrix_sync(
                    bf, &B_sm[(warp_n * 64 + nt * 16) * GP + kk], GP);
#pragma unroll
                for (int mt = 0; mt < 2; mt++)
                    wmma::mma_sync(acc[mt][nt], af[mt], bf, acc[mt][nt]);
            }
        }
        __syncthreads();
    }

    // ---- epilogue: stage each 16x16 tile through per-warp smem scratch,
    //      add bias, convert fp16, store to g_half[0] ----
    float* scratch = reinterpret_cast<float*>(A_sm) + wid * 256;  // 1KB/warp
    const int er = lane >> 1;          // 0..15: row within tile
    const int ec = (lane & 1) * 8;     // 0 or 8: col start within tile

#pragma unroll
    for (int mt = 0; mt < 2; mt++) {
#pragma unroll
        for (int nt = 0; nt < 4; nt++) {
            wmma::store_matrix_sync(scratch, acc[mt][nt], 16, wmma::mem_row_major);
            __syncwarp();
            const int grow = row0 + warp_m * 32 + mt * 16 + er;
            const int gcol = warp_n * 64 + nt * 16 + ec;
            if (grow < N_NODES) {
                const float4 b0 = __ldg(reinterpret_cast<const float4*>(bias + gcol));
                const float4 b1 = __ldg(reinterpret_cast<const float4*>(bias + gcol + 4));
                const float* s = scratch + er * 16 + ec;
                __half2 h0 = __floats2half2_rn(s[0] + b0.x, s[1] + b0.y);
                __half2 h1 = __floats2half2_rn(s[2] + b0.z, s[3] + b0.w);
                __half2 h2 = __floats2half2_rn(s[4] + b1.x, s[5] + b1.y);
                __half2 h3 = __floats2half2_rn(s[6] + b1.z, s[7] + b1.w);
                uint4 pk;
                pk.x = *reinterpret_cast<const unsigned int*>(&h0);
                pk.y = *reinterpret_cast<const unsigned int*>(&h1);
                pk.z = *reinterpret_cast<const unsigned int*>(&h2);
                pk.w = *reinterpret_cast<const unsigned int*>(&h3);
                *reinterpret_cast<uint4*>(
                    &g_half[0][(size_t)grow * H_DIM + gcol]) = pk;
            }
            __syncwarp();
        }
    }
}

// ---------------------------------------------------------------------------
// SpMM (COO + RED), fp16 gather source, fp32 RED target. (round-8 champion)
// ---------------------------------------------------------------------------
__global__ __launch_bounds__(256) void spmm_kernel(const int* __restrict__ rows_base,
                                                   const int* __restrict__ idxp,
                                                   int src_id, int dst_id) {
    const int lane  = threadIdx.x & 31;
    const int chunk = (blockIdx.x * blockDim.x + threadIdx.x) >> 5;
    if (chunk >= NNZ_C / 32) return;

    const int a = __ldg(idxp);
    const __half* __restrict__ src = g_half[src_id];
    float*        __restrict__ dst = g_acc[dst_id];

    const size_t e0 = (size_t)chunk * 32;
    const int  myrow = __ldg(rows_base + (size_t)a * NNZ_C + e0 + lane);
    const int2 mycv  = __ldg(&g_ecv[a][e0 + lane]);

#pragma unroll
    for (int j = 0; j < 32; j++) {
        const int   row = __shfl_sync(0xFFFFFFFFu, myrow, j);
        const int   col = __shfl_sync(0xFFFFFFFFu, mycv.x, j);
        const float val = __int_as_float(__shfl_sync(0xFFFFFFFFu, mycv.y, j));

        const uint2 hv = __ldg(reinterpret_cast<const uint2*>(
                                   src + (size_t)col * H_DIM) + lane);
        const float2 f01 = __half22float2(*reinterpret_cast<const __half2*>(&hv.x));
        const float2 f23 = __half22float2(*reinterpret_cast<const __half2*>(&hv.y));

        float* p = dst + (size_t)row * H_DIM + lane * 4;
        asm volatile("red.global.add.v4.f32 [%0], {%1, %2, %3, %4};"
                     :: "l"(p), "f"(f01.x * val), "f"(f01.y * val),
                        "f"(f23.x * val), "f"(f23.y * val)
                     : "memory");
    }
}

// ---------------------------------------------------------------------------
// Convert fp32 accumulator sid into fp16 mirror sid+1
// ---------------------------------------------------------------------------
__global__ __launch_bounds__(256) void tohalf_kernel(int sid) {
    const size_t i = (size_t)blockIdx.x * blockDim.x + threadIdx.x;
    const size_t n4 = (size_t)N_NODES * H_DIM / 4;
    if (i >= n4) return;
    const float4 v = reinterpret_cast<const float4*>(&g_acc[sid][0])[i];
    __half2 h0 = __floats2half2_rn(v.x, v.y);
    __half2 h1 = __floats2half2_rn(v.z, v.w);
    uint2 pk;
    pk.x = *reinterpret_cast<const unsigned int*>(&h0);
    pk.y = *reinterpret_cast<const unsigned int*>(&h1);
    reinterpret_cast<uint2*>(&g_half[sid + 1][0])[i] = pk;
}

// ---------------------------------------------------------------------------
// LayerNorm + exact-erf GELU, one warp per row (reads fp32 s3)
// ---------------------------------------------------------------------------
__global__ __launch_bounds__(256) void ln_gelu_kernel(const float* __restrict__ gamma,
                                                      const float* __restrict__ beta,
                                                      float* __restrict__ out) {
    const int warp = (blockIdx.x * blockDim.x + threadIdx.x) >> 5;
    const int lane = threadIdx.x & 31;
    if (warp >= N_NODES) return;

    const float* yrow = g_acc[2] + (size_t)warp * H_DIM;
    const float4 v = *reinterpret_cast<const float4*>(yrow + lane * 4);

    float s  = v.x + v.y + v.z + v.w;
    float sq = v.x * v.x + v.y * v.y + v.z * v.z + v.w * v.w;
#pragma unroll
    for (int o = 16; o; o >>= 1) {
        s  += __shfl_xor_sync(0xFFFFFFFFu, s,  o);
        sq += __shfl_xor_sync(0xFFFFFFFFu, sq, o);
    }
    const float mean = s * (1.f / H_DIM);
    const float var  = sq * (1.f / H_DIM) - mean * mean;
    const float rstd = rsqrtf(var + LN_EPS);

    const float4 g = *reinterpret_cast<const float4*>(gamma + lane * 4);
    const float4 b = *reinterpret_cast<const float4*>(beta  + lane * 4);

    auto gelu = [](float t) {
        return 0.5f * t * (1.f + erff(t * 0.7071067811865476f));
    };
    float4 r;
    r.x = gelu((v.x - mean) * rstd * g.x + b.x);
    r.y = gelu((v.y - mean) * rstd * g.y + b.y);
    r.z = gelu((v.z - mean) * rstd * g.z + b.z);
    r.w = gelu((v.w - mean) * rstd * g.w + b.w);

    *reinterpret_cast<float4*>(out + (size_t)warp * H_DIM + lane * 4) = r;
}

// ---------------------------------------------------------------------------
// kernel_launch
// inputs: x, adj_rows, adj_cols, adj_vals, idxes_seq, idxes_res,
//         W, b, gamma, beta
// ---------------------------------------------------------------------------
extern "C" void kernel_launch(void* const* d_in, const int* in_sizes, int n_in,
                              void* d_out, int out_size) {
    const float* x        = (const float*)d_in[0];
    const int*   adj_rows = (const int*)  d_in[1];
    const int*   adj_cols = (const int*)  d_in[2];
    const float* adj_vals = (const float*)d_in[3];
    const int*   idx_seq  = (const int*)  d_in[4];
    const int*   idx_res  = (const int*)  d_in[5];
    const float* W        = (const float*)d_in[6];
    const float* b        = (const float*)d_in[7];
    const float* gamma    = (const float*)d_in[8];
    const float* beta     = (const float*)d_in[9];
    float*       out      = (float*)d_out;

    zero_kernel<<<1024, 256>>>();
    zip_kernel<<<(N_ADJ * NNZ_C + 255) / 256, 256>>>(adj_cols, adj_vals);
    gemm_kernel<<<(N_NODES + 127) / 128, 256>>>(x, W, b);   // -> g_half[0]

    const int SPMM_GRID = (NNZ_C / 32 * 32 + 255) / 256;    // 25000 warps
    const int CVT_GRID  = (N_NODES * H_DIM / 4 + 255) / 256;

    // s1 (acc0) = A[seq0] @ h0
    spmm_kernel<<<SPMM_GRID, 256>>>(adj_rows, idx_seq + 0, 0, 0);
    tohalf_kernel<<<CVT_GRID, 256>>>(0);                    // h1 = fp16(s1)
    // s2 (acc1) = A[seq1] @ h1 + A[res0] @ h0
    spmm_kernel<<<SPMM_GRID, 256>>>(adj_rows, idx_seq + 1, 1, 1);
    spmm_kernel<<<SPMM_GRID, 256>>>(adj_rows, idx_res + 0, 0, 1);
    tohalf_kernel<<<CVT_GRID, 256>>>(1);                    // h2 = fp16(s2)
    // s3 (acc2) = A[seq2] @ h2 + A[res1] @ h0 + A[res2] @ h1
    spmm_kernel<<<SPMM_GRID, 256>>>(adj_rows, idx_seq + 2, 2, 2);
    spmm_kernel<<<SPMM_GRID, 256>>>(adj_rows, idx_res + 1, 0, 2);
    spmm_kernel<<<SPMM_GRID, 256>>>(adj_rows, idx_res + 2, 1, 2);

    ln_gelu_kernel<<<(N_NODES * 32 + 255) / 256, 256>>>(gamma, beta, out);
}